// round 7
// baseline (speedup 1.0000x reference)
#include <cuda_runtime.h>
#include <cuda_fp16.h>
#include <cstdint>

#define N_NODES 8192
#define N_EDGES 65536
#define D_IN    768
#define D_HID   768
#define H1      8
#define D1      (H1 * D_HID)   // 6144

// ---------------- scratch (static device globals) ---------------------------
__device__ __half g_h1f[(size_t)N_NODES * D1];    // fp16 x@W1
__device__ float  g_h2[(size_t)N_NODES * D_HID];  // fp32 out1@W2 (atomic accum)
__device__ __half g_xf[(size_t)N_NODES * D_IN];   // fp16(x)
__device__ __half g_w1h[(size_t)D_IN * D1];
__device__ __half g_w1l[(size_t)D_IN * D1];
__device__ __half g_w2h[(size_t)D1 * D_HID];
__device__ __half g_w2l[(size_t)D1 * D_HID];
__device__ __half g_o1f[(size_t)N_NODES * D1];    // fp16(out1)
__device__ float  g_as1[N_NODES * H1];
__device__ float  g_ad1[N_NODES * H1];
__device__ float  g_aE1[(size_t)N_EDGES * H1];
__device__ float  g_as2[N_NODES];
__device__ float  g_ad2[N_NODES];
__device__ float  g_aE2[N_EDGES];
__device__ int    g_cnt[N_NODES];
__device__ int    g_indptr[N_NODES + 1];
__device__ int    g_cur[N_NODES];
__device__ int    g_eord[N_EDGES];

// ---------------- one-shot zeroing (as1, ad1, as2, ad2, h2) ------------------
__global__ void k_zero_all(float* __restrict__ as1, float* __restrict__ ad1,
                           float* __restrict__ as2, float* __restrict__ ad2,
                           float4* __restrict__ h2v) {
    int i = blockIdx.x * blockDim.x + threadIdx.x;   // 0 .. 1572863
    h2v[i] = make_float4(0.f, 0.f, 0.f, 0.f);
    if (i < N_NODES * H1) { as1[i] = 0.f; ad1[i] = 0.f; }
    if (i < N_NODES) { as2[i] = 0.f; ad2[i] = 0.f; }
}

// ---------------- CSR build ------------------------------------------------
__global__ void k_zero_cnt() {
    int i = blockIdx.x * blockDim.x + threadIdx.x;
    if (i < N_NODES) g_cnt[i] = 0;
}
__global__ void k_count(const int* __restrict__ dst) {
    int e = blockIdx.x * blockDim.x + threadIdx.x;
    if (e < N_EDGES) atomicAdd(&g_cnt[dst[e]], 1);
}
__global__ void k_scan() {
    __shared__ int sh[1024];
    int t = threadIdx.x;
    int base = t * 8;
    int local[8];
    int s = 0;
#pragma unroll
    for (int i = 0; i < 8; i++) { local[i] = s; s += g_cnt[base + i]; }
    sh[t] = s;
    __syncthreads();
    for (int off = 1; off < 1024; off <<= 1) {
        int v = (t >= off) ? sh[t - off] : 0;
        __syncthreads();
        sh[t] += v;
        __syncthreads();
    }
    int prefix = (t == 0) ? 0 : sh[t - 1];
#pragma unroll
    for (int i = 0; i < 8; i++) {
        int v = prefix + local[i];
        g_indptr[base + i] = v;
        g_cur[base + i] = v;
    }
    if (t == 1023) g_indptr[N_NODES] = sh[1023];
}
__global__ void k_scatter(const int* __restrict__ dst) {
    int e = blockIdx.x * blockDim.x + threadIdx.x;
    if (e < N_EDGES) {
        int d = dst[e];
        int p = atomicAdd(&g_cur[d], 1);
        g_eord[p] = e;
    }
}

// ---------------- fp32 -> fp16 round / split ---------------------------------
__global__ void k_round4(const float4* __restrict__ in, uint2* __restrict__ o, int n4) {
    int i = blockIdx.x * blockDim.x + threadIdx.x;
    if (i >= n4) return;
    float4 v = in[i];
    __half2 lo = __floats2half2_rn(v.x, v.y);
    __half2 hi = __floats2half2_rn(v.z, v.w);
    uint2 r;
    r.x = *(uint32_t*)&lo;
    r.y = *(uint32_t*)&hi;
    o[i] = r;
}
__global__ void k_split4(const float4* __restrict__ in,
                         uint2* __restrict__ hi, uint2* __restrict__ lo, int n4) {
    int i = blockIdx.x * blockDim.x + threadIdx.x;
    if (i >= n4) return;
    float4 v = in[i];
    __half hx = __float2half_rn(v.x), hy = __float2half_rn(v.y);
    __half hz = __float2half_rn(v.z), hw = __float2half_rn(v.w);
    __half lx = __float2half_rn(v.x - __half2float(hx));
    __half ly = __float2half_rn(v.y - __half2float(hy));
    __half lz = __float2half_rn(v.z - __half2float(hz));
    __half lw = __float2half_rn(v.w - __half2float(hw));
    uint2 hv, lv;
    hv.x = ((uint32_t)__half_as_ushort(hy) << 16) | __half_as_ushort(hx);
    hv.y = ((uint32_t)__half_as_ushort(hw) << 16) | __half_as_ushort(hz);
    lv.x = ((uint32_t)__half_as_ushort(ly) << 16) | __half_as_ushort(lx);
    lv.y = ((uint32_t)__half_as_ushort(lw) << 16) | __half_as_ushort(lz);
    hi[i] = hv;
    lo[i] = lv;
}

// ---------------- tensor-core GEMM core (2x fp16 product) --------------------
// BK=64, 3-stage cp.async pipeline, BM=BN=128, 8 warps (4x2).
#define BKC 64
#define A_PAD 72                   // 64 data + 8 pad (halfs)
#define B_PAD 136                  // 128 data + 8 pad
#define A_HALFS (128 * A_PAD)      // 9216
#define B_HALFS (BKC * B_PAD)      // 8704
#define STG_HALFS (A_HALFS + 2 * B_HALFS)   // 26624
#define SMEM_BYTES (3 * STG_HALFS * 2)      // 159744

#define LDSM4(R, addr) \
    asm volatile("ldmatrix.sync.aligned.m8n8.x4.shared.b16 {%0,%1,%2,%3}, [%4];" \
        : "=r"(R[0]), "=r"(R[1]), "=r"(R[2]), "=r"(R[3]) : "r"(addr))

#define LDSM4T(R0, R1, R2, R3, addr) \
    asm volatile("ldmatrix.sync.aligned.m8n8.x4.trans.shared.b16 {%0,%1,%2,%3}, [%4];" \
        : "=r"(R0), "=r"(R1), "=r"(R2), "=r"(R3) : "r"(addr))

#define MMA16816(D, A, B) \
    asm volatile("mma.sync.aligned.m16n8k16.row.col.f32.f16.f16.f32 " \
        "{%0,%1,%2,%3}, {%4,%5,%6,%7}, {%8,%9}, {%0,%1,%2,%3};" \
        : "+f"(D[0]), "+f"(D[1]), "+f"(D[2]), "+f"(D[3]) \
        : "r"(A[0]), "r"(A[1]), "r"(A[2]), "r"(A[3]), "r"(B[0]), "r"(B[1]))

__device__ __forceinline__ void cp16(uint32_t saddr, const void* g) {
    asm volatile("cp.async.cg.shared.global [%0], [%1], 16;" :: "r"(saddr), "l"(g));
}

// Mainloop macro; defines c[2][8][4] accumulators plus bm/bn/wm/wn/lane.
// Per-stage copy plan (exact coverage):
//   A: 128 rows x 128B = 1024 chunks -> 4 per thread (idx>>3 = row, 8 chunks/row)
//   B (each of hi/lo): 64 rows x 256B = 1024 chunks -> 4 per thread
//     (idx>>4 = row, 16 chunks/row)
#define GEMM_MAINLOOP(Af, Bh, Bl, Kdim, NKT)                                        \
    extern __shared__ __half smem[];                                               \
    const uint32_t sbase = (uint32_t)__cvta_generic_to_shared(smem);                \
    const int tid = threadIdx.x;                                                    \
    const int lane = tid & 31;                                                      \
    const int wid = tid >> 5;                                                       \
    const int wm = (wid & 3) * 32;                                                  \
    const int wn = (wid >> 2) * 64;                                                 \
    const int bm = blockIdx.y * 128;                                                \
    const int bn = blockIdx.x * 128;                                                \
    float c[2][8][4];                                                               \
    _Pragma("unroll") for (int mi = 0; mi < 2; mi++)                                \
        _Pragma("unroll") for (int nj = 0; nj < 8; nj++)                            \
            _Pragma("unroll") for (int q = 0; q < 4; q++) c[mi][nj][q] = 0.f;       \
    auto load_stage = [&](int stage, int kt) {                                      \
        uint32_t aF = sbase + stage * STG_HALFS * 2;                                \
        uint32_t bHs = aF + A_HALFS * 2;                                            \
        uint32_t bLs = bHs + B_HALFS * 2;                                           \
        _Pragma("unroll") for (int i = 0; i < 4; i++) {                             \
            int idx = tid + i * 256;                                                \
            int ar = idx >> 3, ac = (idx & 7) * 8;                                  \
            cp16(aF + (ar * A_PAD + ac) * 2,                                        \
                 (Af) + (size_t)(bm + ar) * (Kdim) + kt + ac);                      \
        }                                                                           \
        _Pragma("unroll") for (int i = 0; i < 4; i++) {                             \
            int idx = tid + i * 256;                                                \
            int br = idx >> 4, bc = (idx & 15) * 8;                                 \
            size_t gb = (size_t)(kt + br) * N + bn + bc;                            \
            uint32_t sb = (br * B_PAD + bc) * 2;                                    \
            cp16(bHs + sb, (Bh) + gb);                                              \
            cp16(bLs + sb, (Bl) + gb);                                              \
        }                                                                           \
        asm volatile("cp.async.commit_group;");                                     \
    };                                                                              \
    load_stage(0, 0);                                                               \
    if ((NKT) > 1) load_stage(1, BKC);                                              \
    for (int it = 0; it < (NKT); it++) {                                            \
        int stage = it % 3;                                                         \
        if (it + 2 < (NKT)) {                                                       \
            load_stage((it + 2) % 3, (it + 2) * BKC);                               \
            asm volatile("cp.async.wait_group 2;");                                 \
        } else if (it + 1 < (NKT)) {                                                \
            asm volatile("cp.async.wait_group 1;");                                 \
        } else {                                                                    \
            asm volatile("cp.async.wait_group 0;");                                 \
        }                                                                           \
        __syncthreads();                                                            \
        uint32_t aF = sbase + stage * STG_HALFS * 2;                                \
        uint32_t bHs = aF + A_HALFS * 2;                                            \
        uint32_t bLs = bHs + B_HALFS * 2;                                           \
        _Pragma("unroll")                                                           \
        for (int ks = 0; ks < BKC; ks += 16) {                                      \
            uint32_t af[2][4];                                                      \
            _Pragma("unroll") for (int mi = 0; mi < 2; mi++) {                      \
                uint32_t off = ((wm + mi * 16 + (lane & 15)) * A_PAD + ks +         \
                                (lane >> 4) * 8) * 2;                               \
                LDSM4(af[mi], aF + off);                                            \
            }                                                                       \
            uint32_t bfh[8][2], bfl[8][2];                                          \
            int gq = lane >> 3;                                                     \
            int brow = ks + (lane & 7) + (gq & 1) * 8;                              \
            int bcol_base = wn + (gq >> 1) * 8;                                     \
            _Pragma("unroll") for (int nj2 = 0; nj2 < 4; nj2++) {                   \
                uint32_t off = (brow * B_PAD + bcol_base + nj2 * 16) * 2;           \
                LDSM4T(bfh[nj2 * 2][0], bfh[nj2 * 2][1],                            \
                       bfh[nj2 * 2 + 1][0], bfh[nj2 * 2 + 1][1], bHs + off);        \
                LDSM4T(bfl[nj2 * 2][0], bfl[nj2 * 2][1],                            \
                       bfl[nj2 * 2 + 1][0], bfl[nj2 * 2 + 1][1], bLs + off);        \
            }                                                                       \
            _Pragma("unroll") for (int mi = 0; mi < 2; mi++)                        \
                _Pragma("unroll") for (int nj = 0; nj < 8; nj++) {                  \
                    MMA16816(c[mi][nj], af[mi], bfh[nj]);                           \
                    MMA16816(c[mi][nj], af[mi], bfl[nj]);                           \
                }                                                                   \
        }                                                                           \
        __syncthreads();                                                            \
    }

// Epilogue attention partial dots (exact fp32) + atomicAdd into as/ad.
#define GEMM_ATTN_EPILOGUE(asArr, adArr, aSvec, aDvec, Hn, headIdx)                 \
    {                                                                               \
        float ds[4] = {0.f, 0.f, 0.f, 0.f}, dd[4] = {0.f, 0.f, 0.f, 0.f};           \
        _Pragma("unroll") for (int mi = 0; mi < 2; mi++)                            \
            _Pragma("unroll") for (int nj = 0; nj < 8; nj++) {                      \
                int col = bn + wn + nj * 8 + (lane & 3) * 2;                        \
                float s0 = (aSvec)[col], s1 = (aSvec)[col + 1];                     \
                float d0 = (aDvec)[col], d1 = (aDvec)[col + 1];                     \
                ds[mi * 2 + 0] += c[mi][nj][0] * s0 + c[mi][nj][1] * s1;            \
                ds[mi * 2 + 1] += c[mi][nj][2] * s0 + c[mi][nj][3] * s1;            \
                dd[mi * 2 + 0] += c[mi][nj][0] * d0 + c[mi][nj][1] * d1;            \
                dd[mi * 2 + 1] += c[mi][nj][2] * d0 + c[mi][nj][3] * d1;            \
            }                                                                       \
        _Pragma("unroll") for (int r = 0; r < 4; r++) {                             \
            ds[r] += __shfl_xor_sync(0xffffffffu, ds[r], 1);                        \
            ds[r] += __shfl_xor_sync(0xffffffffu, ds[r], 2);                        \
            dd[r] += __shfl_xor_sync(0xffffffffu, dd[r], 1);                        \
            dd[r] += __shfl_xor_sync(0xffffffffu, dd[r], 2);                        \
        }                                                                           \
        if ((lane & 3) == 0) {                                                      \
            _Pragma("unroll") for (int mi = 0; mi < 2; mi++) {                      \
                int ra = bm + wm + mi * 16 + (lane >> 2);                           \
                atomicAdd(&(asArr)[(size_t)ra * (Hn) + (headIdx)], ds[mi * 2 + 0]); \
                atomicAdd(&(asArr)[(size_t)(ra + 8) * (Hn) + (headIdx)], ds[mi * 2 + 1]); \
                atomicAdd(&(adArr)[(size_t)ra * (Hn) + (headIdx)], dd[mi * 2 + 0]); \
                atomicAdd(&(adArr)[(size_t)(ra + 8) * (Hn) + (headIdx)], dd[mi * 2 + 1]); \
            }                                                                       \
        }                                                                           \
    }

// GEMM1: C fp16 direct store + attention dots for H1 heads.
__global__ __launch_bounds__(256) void k_gemm1(
    const __half* __restrict__ Af,
    const __half* __restrict__ Bh, const __half* __restrict__ Bl,
    __half* __restrict__ Cf, float* __restrict__ asArr, float* __restrict__ adArr,
    const float* __restrict__ aSvec, const float* __restrict__ aDvec,
    int N, int K) {
    GEMM_MAINLOOP(Af, Bh, Bl, K, K / BKC)

    const int head = bn / D_HID;
    GEMM_ATTN_EPILOGUE(asArr, adArr, aSvec, aDvec, H1, head)

#pragma unroll
    for (int mi = 0; mi < 2; mi++) {
        int row0 = bm + wm + mi * 16 + (lane >> 2);
#pragma unroll
        for (int nj = 0; nj < 8; nj++) {
            int col = bn + wn + nj * 8 + (lane & 3) * 2;
            __half2 p0 = __floats2half2_rn(c[mi][nj][0], c[mi][nj][1]);
            __half2 p1 = __floats2half2_rn(c[mi][nj][2], c[mi][nj][3]);
            *(__half2*)(Cf + (size_t)row0 * N + col) = p0;
            *(__half2*)(Cf + (size_t)(row0 + 8) * N + col) = p1;
        }
    }
}

// GEMM2: split-K over blockIdx.z, fp32 atomicAdd epilogue + attention dots (H=1).
__global__ __launch_bounds__(256) void k_gemm2(
    const __half* __restrict__ Afull,
    const __half* __restrict__ Bhfull, const __half* __restrict__ Blfull,
    float* __restrict__ C, float* __restrict__ asArr, float* __restrict__ adArr,
    const float* __restrict__ aSvec, const float* __restrict__ aDvec,
    int N, int Kfull, int ksplit) {
    const int kpart = Kfull / ksplit;
    const int kbase = blockIdx.z * kpart;
    const __half* Af = Afull + kbase;            // row stride remains Kfull
    const __half* Bh = Bhfull + (size_t)kbase * N;
    const __half* Bl = Blfull + (size_t)kbase * N;

    GEMM_MAINLOOP(Af, Bh, Bl, Kfull, kpart / BKC)

    GEMM_ATTN_EPILOGUE(asArr, adArr, aSvec, aDvec, 1, 0)

#pragma unroll
    for (int mi = 0; mi < 2; mi++) {
        int row0 = bm + wm + mi * 16 + (lane >> 2);
#pragma unroll
        for (int nj = 0; nj < 8; nj++) {
            int col = bn + wn + nj * 8 + (lane & 3) * 2;
            float* p0 = C + (size_t)row0 * N + col;
            float* p1 = C + (size_t)(row0 + 8) * N + col;
            atomicAdd(p0, c[mi][nj][0]);
            atomicAdd(p0 + 1, c[mi][nj][1]);
            atomicAdd(p1, c[mi][nj][2]);
            atomicAdd(p1 + 1, c[mi][nj][3]);
        }
    }
}

// ---------------- segment softmax over CSR -----------------------------------
__global__ void k_softmax(const int* __restrict__ src,
                          const float* __restrict__ as,
                          const float* __restrict__ ad,
                          float* __restrict__ aE, int H) {
    int n = blockIdx.x;
    int hh = threadIdx.x >> 5;
    int lane = threadIdx.x & 31;
    int beg = g_indptr[n], end = g_indptr[n + 1];
    if (beg == end) return;
    float adn = ad[(size_t)n * H + hh];

    float m = -3.4e38f;
    for (int j = beg + lane; j < end; j += 32) {
        int s = src[g_eord[j]];
        float v = as[(size_t)s * H + hh] + adn;
        v = v > 0.f ? v : 0.2f * v;
        m = fmaxf(m, v);
    }
#pragma unroll
    for (int o = 16; o; o >>= 1) m = fmaxf(m, __shfl_xor_sync(0xffffffffu, m, o));

    float sum = 0.f;
    for (int j = beg + lane; j < end; j += 32) {
        int s = src[g_eord[j]];
        float v = as[(size_t)s * H + hh] + adn;
        v = v > 0.f ? v : 0.2f * v;
        float ex = __expf(v - m);
        aE[(size_t)j * H + hh] = ex;
        sum += ex;
    }
#pragma unroll
    for (int o = 16; o; o >>= 1) sum += __shfl_xor_sync(0xffffffffu, sum, o);

    float inv = 1.f / (sum + 1e-16f);
    for (int j = beg + lane; j < end; j += 32)
        aE[(size_t)j * H + hh] *= inv;
}

// ---------------- aggregation layer 1: fp16 gather -> fp16 out ---------------
__global__ __launch_bounds__(192) void k_aggregate_l1(const int* __restrict__ src,
                                                      const __half* __restrict__ hf,
                                                      const float* __restrict__ aE,
                                                      const float* __restrict__ bias,
                                                      __half* __restrict__ of) {
    int n = blockIdx.x;
    int hh = blockIdx.y;
    int t = threadIdx.x;
    int beg = g_indptr[n], end = g_indptr[n + 1];

    float a0 = 0.f, a1 = 0.f, a2 = 0.f, a3 = 0.f;
    for (int j = beg; j < end; j++) {
        int s = src[g_eord[j]];
        float w = aE[(size_t)j * H1 + hh];
        uint2 rv = *(const uint2*)(hf + ((size_t)s * H1 + hh) * D_HID + t * 4);
        __half2 h01 = *(__half2*)&rv.x;
        __half2 h23 = *(__half2*)&rv.y;
        float2 f01 = __half22float2(h01);
        float2 f23 = __half22float2(h23);
        a0 += f01.x * w;
        a1 += f01.y * w;
        a2 += f23.x * w;
        a3 += f23.y * w;
    }
    const float4 bb = *(const float4*)(bias + (size_t)hh * D_HID + t * 4);
    float v0 = a0 + bb.x;
    float v1 = a1 + bb.y;
    float v2 = a2 + bb.z;
    float v3 = a3 + bb.w;
    v0 = v0 > 0.f ? v0 : (__expf(v0) - 1.f);
    v1 = v1 > 0.f ? v1 : (__expf(v1) - 1.f);
    v2 = v2 > 0.f ? v2 : (__expf(v2) - 1.f);
    v3 = v3 > 0.f ? v3 : (__expf(v3) - 1.f);
    __half2 lo = __floats2half2_rn(v0, v1);
    __half2 hi = __floats2half2_rn(v2, v3);
    uint2 r;
    r.x = *(uint32_t*)&lo;
    r.y = *(uint32_t*)&hi;
    *(uint2*)(of + ((size_t)n * H1 + hh) * D_HID + t * 4) = r;
}

// ---------------- aggregation layer 2: fp32, no ELU ---------------------------
__global__ __launch_bounds__(192) void k_aggregate_l2(const int* __restrict__ src,
                                                      const float* __restrict__ h,
                                                      const float* __restrict__ aE,
                                                      const float* __restrict__ bias,
                                                      float* __restrict__ out) {
    int n = blockIdx.x;
    int t = threadIdx.x;
    int beg = g_indptr[n], end = g_indptr[n + 1];

    float a0 = 0.f, a1 = 0.f, a2 = 0.f, a3 = 0.f;
    for (int j = beg; j < end; j++) {
        int s = src[g_eord[j]];
        float w = aE[j];
        float4 v = *(const float4*)(h + (size_t)s * D_HID + t * 4);
        a0 += v.x * w;
        a1 += v.y * w;
        a2 += v.z * w;
        a3 += v.w * w;
    }
    const float4 bb = *(const float4*)(bias + t * 4);
    float4 o = {a0 + bb.x, a1 + bb.y, a2 + bb.z, a3 + bb.w};
    *(float4*)(out + (size_t)n * D_HID + t * 4) = o;
}

// ---------------- launch ----------------------------------------------------
extern "C" void kernel_launch(void* const* d_in, const int* in_sizes, int n_in,
                              void* d_out, int out_size) {
    const float* x      = (const float*)d_in[0];
    const float* W1     = (const float*)d_in[1];
    const float* a_src1 = (const float*)d_in[2];
    const float* a_dst1 = (const float*)d_in[3];
    const float* b1     = (const float*)d_in[4];
    const float* W2     = (const float*)d_in[5];
    const float* a_src2 = (const float*)d_in[6];
    const float* a_dst2 = (const float*)d_in[7];
    const float* b2     = (const float*)d_in[8];
    const int*   el     = (const int*)d_in[9];
    const int* srcA = el;
    const int* dstA = el + N_EDGES;
    float* out = (float*)d_out;

    float *p_h2, *p_as1, *p_ad1, *p_aE1, *p_as2, *p_ad2, *p_aE2;
    __half *p_h1f, *p_xf, *p_w1h, *p_w1l, *p_w2h, *p_w2l, *p_o1f;
    cudaGetSymbolAddress((void**)&p_h1f, g_h1f);
    cudaGetSymbolAddress((void**)&p_h2,  g_h2);
    cudaGetSymbolAddress((void**)&p_xf,  g_xf);
    cudaGetSymbolAddress((void**)&p_w1h, g_w1h);
    cudaGetSymbolAddress((void**)&p_w1l, g_w1l);
    cudaGetSymbolAddress((void**)&p_w2h, g_w2h);
    cudaGetSymbolAddress((void**)&p_w2l, g_w2l);
    cudaGetSymbolAddress((void**)&p_o1f, g_o1f);
    cudaGetSymbolAddress((void**)&p_as1, g_as1);
    cudaGetSymbolAddress((void**)&p_ad1, g_ad1);
    cudaGetSymbolAddress((void**)&p_aE1, g_aE1);
    cudaGetSymbolAddress((void**)&p_as2, g_as2);
    cudaGetSymbolAddress((void**)&p_ad2, g_ad2);
    cudaGetSymbolAddress((void**)&p_aE2, g_aE2);

    static bool s_attr_done = false;
    if (!s_attr_done) {
        cudaFuncSetAttribute(k_gemm1, cudaFuncAttributeMaxDynamicSharedMemorySize,
                             SMEM_BYTES);
        cudaFuncSetAttribute(k_gemm2, cudaFuncAttributeMaxDynamicSharedMemorySize,
                             SMEM_BYTES);
        s_attr_done = true;
    }

    // 1: zero all accumulators (h2 float4 grid covers 6144*1024 exactly)
    k_zero_all<<<N_NODES * D_HID / 4 / 256, 256>>>(p_as1, p_ad1, p_as2, p_ad2,
                                                   (float4*)p_h2);
    // 2-3: operands for GEMM1
    k_round4<<<(N_NODES * D_IN / 4 + 255) / 256, 256>>>(
        (const float4*)x, (uint2*)p_xf, N_NODES * D_IN / 4);
    k_split4<<<(D_IN * D1 / 4 + 255) / 256, 256>>>(
        (const float4*)W1, (uint2*)p_w1h, (uint2*)p_w1l, D_IN * D1 / 4);

    // 4: GEMM1 (profiled slot): h1f = fp16(x @ W1) + fused attention dots
    dim3 g1(D1 / 128, N_NODES / 128);
    k_gemm1<<<g1, 256, SMEM_BYTES>>>(p_xf, p_w1h, p_w1l, p_h1f,
                                     p_as1, p_ad1, a_src1, a_dst1, D1, D_IN);

    // 5: W2 split (needed only by GEMM2)
    k_split4<<<(D1 * D_HID / 4 + 255) / 256, 256>>>(
        (const float4*)W2, (uint2*)p_w2h, (uint2*)p_w2l, D1 * D_HID / 4);

    // 6-9: CSR build (needed from softmax onward)
    k_zero_cnt<<<N_NODES / 256, 256>>>();
    k_count<<<N_EDGES / 256, 256>>>(dstA);
    k_scan<<<1, 1024>>>();
    k_scatter<<<N_EDGES / 256, 256>>>(dstA);

    // Layer 1 edge ops
    k_softmax<<<N_NODES, 32 * H1>>>(srcA, p_as1, p_ad1, p_aE1, H1);
    dim3 ga1(N_NODES, H1);
    k_aggregate_l1<<<ga1, 192>>>(srcA, p_h1f, p_aE1, b1, p_o1f);

    // Layer 2: h2 = out1 @ W2 (split-K=2, atomic accumulate), attn fused
    dim3 g2(D_HID / 128, N_NODES / 128, 2);
    k_gemm2<<<g2, 256, SMEM_BYTES>>>(p_o1f, p_w2h, p_w2l, p_h2,
                                     p_as2, p_ad2, a_src2, a_dst2, D_HID, D1, 2);
    k_softmax<<<N_NODES, 32>>>(srcA, p_as2, p_ad2, p_aE2, 1);
    k_aggregate_l2<<<N_NODES, 192>>>(srcA, p_h2, p_aE2, b2, out);
}

// round 8
// speedup vs baseline: 1.1383x; 1.1383x over previous
#include <cuda_runtime.h>
#include <cuda_fp16.h>
#include <cstdint>

#define N_NODES 8192
#define N_EDGES 65536
#define D_IN    768
#define D_HID   768
#define H1      8
#define D1      (H1 * D_HID)   // 6144

// ---------------- scratch (static device globals) ---------------------------
__device__ __half g_h1f[(size_t)N_NODES * D1];    // fp16 x@W1
__device__ float  g_h2[(size_t)N_NODES * D_HID];  // fp32 out1@W2 (atomic accum)
__device__ __half g_xf[(size_t)N_NODES * D_IN];   // fp16(x)
__device__ __half g_w1h[(size_t)D_IN * D1];
__device__ __half g_w1l[(size_t)D_IN * D1];
__device__ __half g_w2h[(size_t)D1 * D_HID];
__device__ __half g_w2l[(size_t)D1 * D_HID];
__device__ __half g_o1f[(size_t)N_NODES * D1];    // fp16(out1)
__device__ float  g_as1[N_NODES * H1];
__device__ float  g_ad1[N_NODES * H1];
__device__ float  g_aE1[(size_t)N_EDGES * H1];
__device__ float  g_as2[N_NODES];
__device__ float  g_ad2[N_NODES];
__device__ float  g_aE2[N_EDGES];
__device__ int    g_cnt[N_NODES];
__device__ int    g_indptr[N_NODES + 1];
__device__ int    g_cur[N_NODES];
__device__ int    g_eord[N_EDGES];

// ---------------- one-shot zeroing (as1, ad1, as2, ad2, h2) ------------------
__global__ void k_zero_all(float* __restrict__ as1, float* __restrict__ ad1,
                           float* __restrict__ as2, float* __restrict__ ad2,
                           float4* __restrict__ h2v) {
    int i = blockIdx.x * blockDim.x + threadIdx.x;   // 0 .. 1572863
    h2v[i] = make_float4(0.f, 0.f, 0.f, 0.f);
    if (i < N_NODES * H1) { as1[i] = 0.f; ad1[i] = 0.f; }
    if (i < N_NODES) { as2[i] = 0.f; ad2[i] = 0.f; }
}

// ---------------- CSR build ------------------------------------------------
__global__ void k_zero_cnt() {
    int i = blockIdx.x * blockDim.x + threadIdx.x;
    if (i < N_NODES) g_cnt[i] = 0;
}
__global__ void k_count(const int* __restrict__ dst) {
    int e = blockIdx.x * blockDim.x + threadIdx.x;
    if (e < N_EDGES) atomicAdd(&g_cnt[dst[e]], 1);
}
__global__ void k_scan() {
    __shared__ int sh[1024];
    int t = threadIdx.x;
    int base = t * 8;
    int local[8];
    int s = 0;
#pragma unroll
    for (int i = 0; i < 8; i++) { local[i] = s; s += g_cnt[base + i]; }
    sh[t] = s;
    __syncthreads();
    for (int off = 1; off < 1024; off <<= 1) {
        int v = (t >= off) ? sh[t - off] : 0;
        __syncthreads();
        sh[t] += v;
        __syncthreads();
    }
    int prefix = (t == 0) ? 0 : sh[t - 1];
#pragma unroll
    for (int i = 0; i < 8; i++) {
        int v = prefix + local[i];
        g_indptr[base + i] = v;
        g_cur[base + i] = v;
    }
    if (t == 1023) g_indptr[N_NODES] = sh[1023];
}
__global__ void k_scatter(const int* __restrict__ dst) {
    int e = blockIdx.x * blockDim.x + threadIdx.x;
    if (e < N_EDGES) {
        int d = dst[e];
        int p = atomicAdd(&g_cur[d], 1);
        g_eord[p] = e;
    }
}

// ---------------- fp32 -> fp16 round / split ---------------------------------
__global__ void k_round4(const float4* __restrict__ in, uint2* __restrict__ o, int n4) {
    int i = blockIdx.x * blockDim.x + threadIdx.x;
    if (i >= n4) return;
    float4 v = in[i];
    __half2 lo = __floats2half2_rn(v.x, v.y);
    __half2 hi = __floats2half2_rn(v.z, v.w);
    uint2 r;
    r.x = *(uint32_t*)&lo;
    r.y = *(uint32_t*)&hi;
    o[i] = r;
}
__global__ void k_split4(const float4* __restrict__ in,
                         uint2* __restrict__ hi, uint2* __restrict__ lo, int n4) {
    int i = blockIdx.x * blockDim.x + threadIdx.x;
    if (i >= n4) return;
    float4 v = in[i];
    __half hx = __float2half_rn(v.x), hy = __float2half_rn(v.y);
    __half hz = __float2half_rn(v.z), hw = __float2half_rn(v.w);
    __half lx = __float2half_rn(v.x - __half2float(hx));
    __half ly = __float2half_rn(v.y - __half2float(hy));
    __half lz = __float2half_rn(v.z - __half2float(hz));
    __half lw = __float2half_rn(v.w - __half2float(hw));
    uint2 hv, lv;
    hv.x = ((uint32_t)__half_as_ushort(hy) << 16) | __half_as_ushort(hx);
    hv.y = ((uint32_t)__half_as_ushort(hw) << 16) | __half_as_ushort(hz);
    lv.x = ((uint32_t)__half_as_ushort(ly) << 16) | __half_as_ushort(lx);
    lv.y = ((uint32_t)__half_as_ushort(lw) << 16) | __half_as_ushort(lz);
    hi[i] = hv;
    lo[i] = lv;
}

// ---------------- tensor-core GEMM core (2x fp16 product) --------------------
// BK=64, 2-stage cp.async pipeline, BM=BN=128, 8 warps (4x2), 2 CTAs/SM.
#define BKC 64
#define A_PAD 72                   // 64 data + 8 pad (halfs)
#define B_PAD 136                  // 128 data + 8 pad
#define A_HALFS (128 * A_PAD)      // 9216
#define B_HALFS (BKC * B_PAD)      // 8704
#define STG_HALFS (A_HALFS + 2 * B_HALFS)   // 26624
#define SMEM_BYTES (2 * STG_HALFS * 2)      // 106496 -> 2 CTAs/SM

#define LDSM4(R, addr) \
    asm volatile("ldmatrix.sync.aligned.m8n8.x4.shared.b16 {%0,%1,%2,%3}, [%4];" \
        : "=r"(R[0]), "=r"(R[1]), "=r"(R[2]), "=r"(R[3]) : "r"(addr))

#define LDSM4T(R0, R1, R2, R3, addr) \
    asm volatile("ldmatrix.sync.aligned.m8n8.x4.trans.shared.b16 {%0,%1,%2,%3}, [%4];" \
        : "=r"(R0), "=r"(R1), "=r"(R2), "=r"(R3) : "r"(addr))

#define MMA16816(D, A, B) \
    asm volatile("mma.sync.aligned.m16n8k16.row.col.f32.f16.f16.f32 " \
        "{%0,%1,%2,%3}, {%4,%5,%6,%7}, {%8,%9}, {%0,%1,%2,%3};" \
        : "+f"(D[0]), "+f"(D[1]), "+f"(D[2]), "+f"(D[3]) \
        : "r"(A[0]), "r"(A[1]), "r"(A[2]), "r"(A[3]), "r"(B[0]), "r"(B[1]))

__device__ __forceinline__ void cp16(uint32_t saddr, const void* g) {
    asm volatile("cp.async.cg.shared.global [%0], [%1], 16;" :: "r"(saddr), "l"(g));
}

// Mainloop macro; defines c[2][8][4] accumulators plus bm/bn/wm/wn/lane.
// Per-stage copy plan (exact coverage):
//   A: 128 rows x 128B = 1024 chunks -> 4 per thread
//   B (each of hi/lo): 64 rows x 256B = 1024 chunks -> 4 per thread
#define GEMM_MAINLOOP(Af, Bh, Bl, Kdim, NKT)                                        \
    extern __shared__ __half smem[];                                               \
    const uint32_t sbase = (uint32_t)__cvta_generic_to_shared(smem);                \
    const int tid = threadIdx.x;                                                    \
    const int lane = tid & 31;                                                      \
    const int wid = tid >> 5;                                                       \
    const int wm = (wid & 3) * 32;                                                  \
    const int wn = (wid >> 2) * 64;                                                 \
    const int bm = blockIdx.y * 128;                                                \
    const int bn = blockIdx.x * 128;                                                \
    float c[2][8][4];                                                               \
    _Pragma("unroll") for (int mi = 0; mi < 2; mi++)                                \
        _Pragma("unroll") for (int nj = 0; nj < 8; nj++)                            \
            _Pragma("unroll") for (int q = 0; q < 4; q++) c[mi][nj][q] = 0.f;       \
    auto load_stage = [&](int stage, int kt) {                                      \
        uint32_t aF = sbase + stage * STG_HALFS * 2;                                \
        uint32_t bHs = aF + A_HALFS * 2;                                            \
        uint32_t bLs = bHs + B_HALFS * 2;                                           \
        _Pragma("unroll") for (int i = 0; i < 4; i++) {                             \
            int idx = tid + i * 256;                                                \
            int ar = idx >> 3, ac = (idx & 7) * 8;                                  \
            cp16(aF + (ar * A_PAD + ac) * 2,                                        \
                 (Af) + (size_t)(bm + ar) * (Kdim) + kt + ac);                      \
        }                                                                           \
        _Pragma("unroll") for (int i = 0; i < 4; i++) {                             \
            int idx = tid + i * 256;                                                \
            int br = idx >> 4, bc = (idx & 15) * 8;                                 \
            size_t gb = (size_t)(kt + br) * N + bn + bc;                            \
            uint32_t sb = (br * B_PAD + bc) * 2;                                    \
            cp16(bHs + sb, (Bh) + gb);                                              \
            cp16(bLs + sb, (Bl) + gb);                                              \
        }                                                                           \
        asm volatile("cp.async.commit_group;");                                     \
    };                                                                              \
    load_stage(0, 0);                                                               \
    for (int it = 0; it < (NKT); it++) {                                            \
        int stage = it & 1;                                                         \
        if (it + 1 < (NKT)) {                                                       \
            load_stage(stage ^ 1, (it + 1) * BKC);                                  \
            asm volatile("cp.async.wait_group 1;");                                 \
        } else {                                                                    \
            asm volatile("cp.async.wait_group 0;");                                 \
        }                                                                           \
        __syncthreads();                                                            \
        uint32_t aF = sbase + stage * STG_HALFS * 2;                                \
        uint32_t bHs = aF + A_HALFS * 2;                                            \
        uint32_t bLs = bHs + B_HALFS * 2;                                           \
        _Pragma("unroll")                                                           \
        for (int ks = 0; ks < BKC; ks += 16) {                                      \
            uint32_t af[2][4];                                                      \
            _Pragma("unroll") for (int mi = 0; mi < 2; mi++) {                      \
                uint32_t off = ((wm + mi * 16 + (lane & 15)) * A_PAD + ks +         \
                                (lane >> 4) * 8) * 2;                               \
                LDSM4(af[mi], aF + off);                                            \
            }                                                                       \
            uint32_t bfh[8][2], bfl[8][2];                                          \
            int gq = lane >> 3;                                                     \
            int brow = ks + (lane & 7) + (gq & 1) * 8;                              \
            int bcol_base = wn + (gq >> 1) * 8;                                     \
            _Pragma("unroll") for (int nj2 = 0; nj2 < 4; nj2++) {                   \
                uint32_t off = (brow * B_PAD + bcol_base + nj2 * 16) * 2;           \
                LDSM4T(bfh[nj2 * 2][0], bfh[nj2 * 2][1],                            \
                       bfh[nj2 * 2 + 1][0], bfh[nj2 * 2 + 1][1], bHs + off);        \
                LDSM4T(bfl[nj2 * 2][0], bfl[nj2 * 2][1],                            \
                       bfl[nj2 * 2 + 1][0], bfl[nj2 * 2 + 1][1], bLs + off);        \
            }                                                                       \
            _Pragma("unroll") for (int mi = 0; mi < 2; mi++)                        \
                _Pragma("unroll") for (int nj = 0; nj < 8; nj++) {                  \
                    MMA16816(c[mi][nj], af[mi], bfh[nj]);                           \
                    MMA16816(c[mi][nj], af[mi], bfl[nj]);                           \
                }                                                                   \
        }                                                                           \
        __syncthreads();                                                            \
    }

// Epilogue attention partial dots (exact fp32) + atomicAdd into as/ad.
#define GEMM_ATTN_EPILOGUE(asArr, adArr, aSvec, aDvec, Hn, headIdx)                 \
    {                                                                               \
        float ds[4] = {0.f, 0.f, 0.f, 0.f}, dd[4] = {0.f, 0.f, 0.f, 0.f};           \
        _Pragma("unroll") for (int mi = 0; mi < 2; mi++)                            \
            _Pragma("unroll") for (int nj = 0; nj < 8; nj++) {                      \
                int col = bn + wn + nj * 8 + (lane & 3) * 2;                        \
                float s0 = (aSvec)[col], s1 = (aSvec)[col + 1];                     \
                float d0 = (aDvec)[col], d1 = (aDvec)[col + 1];                     \
                ds[mi * 2 + 0] += c[mi][nj][0] * s0 + c[mi][nj][1] * s1;            \
                ds[mi * 2 + 1] += c[mi][nj][2] * s0 + c[mi][nj][3] * s1;            \
                dd[mi * 2 + 0] += c[mi][nj][0] * d0 + c[mi][nj][1] * d1;            \
                dd[mi * 2 + 1] += c[mi][nj][2] * d0 + c[mi][nj][3] * d1;            \
            }                                                                       \
        _Pragma("unroll") for (int r = 0; r < 4; r++) {                             \
            ds[r] += __shfl_xor_sync(0xffffffffu, ds[r], 1);                        \
            ds[r] += __shfl_xor_sync(0xffffffffu, ds[r], 2);                        \
            dd[r] += __shfl_xor_sync(0xffffffffu, dd[r], 1);                        \
            dd[r] += __shfl_xor_sync(0xffffffffu, dd[r], 2);                        \
        }                                                                           \
        if ((lane & 3) == 0) {                                                      \
            _Pragma("unroll") for (int mi = 0; mi < 2; mi++) {                      \
                int ra = bm + wm + mi * 16 + (lane >> 2);                           \
                atomicAdd(&(asArr)[(size_t)ra * (Hn) + (headIdx)], ds[mi * 2 + 0]); \
                atomicAdd(&(asArr)[(size_t)(ra + 8) * (Hn) + (headIdx)], ds[mi * 2 + 1]); \
                atomicAdd(&(adArr)[(size_t)ra * (Hn) + (headIdx)], dd[mi * 2 + 0]); \
                atomicAdd(&(adArr)[(size_t)(ra + 8) * (Hn) + (headIdx)], dd[mi * 2 + 1]); \
            }                                                                       \
        }                                                                           \
    }

// GEMM1: C fp16 direct store + attention dots for H1 heads.
__global__ __launch_bounds__(256, 2) void k_gemm1(
    const __half* __restrict__ Af,
    const __half* __restrict__ Bh, const __half* __restrict__ Bl,
    __half* __restrict__ Cf, float* __restrict__ asArr, float* __restrict__ adArr,
    const float* __restrict__ aSvec, const float* __restrict__ aDvec,
    int N, int K) {
    GEMM_MAINLOOP(Af, Bh, Bl, K, K / BKC)

    const int head = bn / D_HID;
    GEMM_ATTN_EPILOGUE(asArr, adArr, aSvec, aDvec, H1, head)

#pragma unroll
    for (int mi = 0; mi < 2; mi++) {
        int row0 = bm + wm + mi * 16 + (lane >> 2);
#pragma unroll
        for (int nj = 0; nj < 8; nj++) {
            int col = bn + wn + nj * 8 + (lane & 3) * 2;
            __half2 p0 = __floats2half2_rn(c[mi][nj][0], c[mi][nj][1]);
            __half2 p1 = __floats2half2_rn(c[mi][nj][2], c[mi][nj][3]);
            *(__half2*)(Cf + (size_t)row0 * N + col) = p0;
            *(__half2*)(Cf + (size_t)(row0 + 8) * N + col) = p1;
        }
    }
}

// GEMM2: split-K over blockIdx.z, fp32 atomicAdd epilogue + attention dots (H=1).
__global__ __launch_bounds__(256, 2) void k_gemm2(
    const __half* __restrict__ Afull,
    const __half* __restrict__ Bhfull, const __half* __restrict__ Blfull,
    float* __restrict__ C, float* __restrict__ asArr, float* __restrict__ adArr,
    const float* __restrict__ aSvec, const float* __restrict__ aDvec,
    int N, int Kfull, int ksplit) {
    const int kpart = Kfull / ksplit;
    const int kbase = blockIdx.z * kpart;
    const __half* Af = Afull + kbase;            // row stride remains Kfull
    const __half* Bh = Bhfull + (size_t)kbase * N;
    const __half* Bl = Blfull + (size_t)kbase * N;

    GEMM_MAINLOOP(Af, Bh, Bl, Kfull, kpart / BKC)

    GEMM_ATTN_EPILOGUE(asArr, adArr, aSvec, aDvec, 1, 0)

#pragma unroll
    for (int mi = 0; mi < 2; mi++) {
        int row0 = bm + wm + mi * 16 + (lane >> 2);
#pragma unroll
        for (int nj = 0; nj < 8; nj++) {
            int col = bn + wn + nj * 8 + (lane & 3) * 2;
            float* p0 = C + (size_t)row0 * N + col;
            float* p1 = C + (size_t)(row0 + 8) * N + col;
            atomicAdd(p0, c[mi][nj][0]);
            atomicAdd(p0 + 1, c[mi][nj][1]);
            atomicAdd(p1, c[mi][nj][2]);
            atomicAdd(p1 + 1, c[mi][nj][3]);
        }
    }
}

// ---------------- segment softmax over CSR -----------------------------------
__global__ void k_softmax(const int* __restrict__ src,
                          const float* __restrict__ as,
                          const float* __restrict__ ad,
                          float* __restrict__ aE, int H) {
    int n = blockIdx.x;
    int hh = threadIdx.x >> 5;
    int lane = threadIdx.x & 31;
    int beg = g_indptr[n], end = g_indptr[n + 1];
    if (beg == end) return;
    float adn = ad[(size_t)n * H + hh];

    float m = -3.4e38f;
    for (int j = beg + lane; j < end; j += 32) {
        int s = src[g_eord[j]];
        float v = as[(size_t)s * H + hh] + adn;
        v = v > 0.f ? v : 0.2f * v;
        m = fmaxf(m, v);
    }
#pragma unroll
    for (int o = 16; o; o >>= 1) m = fmaxf(m, __shfl_xor_sync(0xffffffffu, m, o));

    float sum = 0.f;
    for (int j = beg + lane; j < end; j += 32) {
        int s = src[g_eord[j]];
        float v = as[(size_t)s * H + hh] + adn;
        v = v > 0.f ? v : 0.2f * v;
        float ex = __expf(v - m);
        aE[(size_t)j * H + hh] = ex;
        sum += ex;
    }
#pragma unroll
    for (int o = 16; o; o >>= 1) sum += __shfl_xor_sync(0xffffffffu, sum, o);

    float inv = 1.f / (sum + 1e-16f);
    for (int j = beg + lane; j < end; j += 32)
        aE[(size_t)j * H + hh] *= inv;
}

// ---------------- aggregation layer 1: fp16 gather -> fp16 out ---------------
__global__ __launch_bounds__(192) void k_aggregate_l1(const int* __restrict__ src,
                                                      const __half* __restrict__ hf,
                                                      const float* __restrict__ aE,
                                                      const float* __restrict__ bias,
                                                      __half* __restrict__ of) {
    int n = blockIdx.x;
    int hh = blockIdx.y;
    int t = threadIdx.x;
    int beg = g_indptr[n], end = g_indptr[n + 1];

    float a0 = 0.f, a1 = 0.f, a2 = 0.f, a3 = 0.f;
    for (int j = beg; j < end; j++) {
        int s = src[g_eord[j]];
        float w = aE[(size_t)j * H1 + hh];
        uint2 rv = *(const uint2*)(hf + ((size_t)s * H1 + hh) * D_HID + t * 4);
        __half2 h01 = *(__half2*)&rv.x;
        __half2 h23 = *(__half2*)&rv.y;
        float2 f01 = __half22float2(h01);
        float2 f23 = __half22float2(h23);
        a0 += f01.x * w;
        a1 += f01.y * w;
        a2 += f23.x * w;
        a3 += f23.y * w;
    }
    const float4 bb = *(const float4*)(bias + (size_t)hh * D_HID + t * 4);
    float v0 = a0 + bb.x;
    float v1 = a1 + bb.y;
    float v2 = a2 + bb.z;
    float v3 = a3 + bb.w;
    v0 = v0 > 0.f ? v0 : (__expf(v0) - 1.f);
    v1 = v1 > 0.f ? v1 : (__expf(v1) - 1.f);
    v2 = v2 > 0.f ? v2 : (__expf(v2) - 1.f);
    v3 = v3 > 0.f ? v3 : (__expf(v3) - 1.f);
    __half2 lo = __floats2half2_rn(v0, v1);
    __half2 hi = __floats2half2_rn(v2, v3);
    uint2 r;
    r.x = *(uint32_t*)&lo;
    r.y = *(uint32_t*)&hi;
    *(uint2*)(of + ((size_t)n * H1 + hh) * D_HID + t * 4) = r;
}

// ---------------- aggregation layer 2: fp32, no ELU ---------------------------
__global__ __launch_bounds__(192) void k_aggregate_l2(const int* __restrict__ src,
                                                      const float* __restrict__ h,
                                                      const float* __restrict__ aE,
                                                      const float* __restrict__ bias,
                                                      float* __restrict__ out) {
    int n = blockIdx.x;
    int t = threadIdx.x;
    int beg = g_indptr[n], end = g_indptr[n + 1];

    float a0 = 0.f, a1 = 0.f, a2 = 0.f, a3 = 0.f;
    for (int j = beg; j < end; j++) {
        int s = src[g_eord[j]];
        float w = aE[j];
        float4 v = *(const float4*)(h + (size_t)s * D_HID + t * 4);
        a0 += v.x * w;
        a1 += v.y * w;
        a2 += v.z * w;
        a3 += v.w * w;
    }
    const float4 bb = *(const float4*)(bias + t * 4);
    float4 o = {a0 + bb.x, a1 + bb.y, a2 + bb.z, a3 + bb.w};
    *(float4*)(out + (size_t)n * D_HID + t * 4) = o;
}

// ---------------- launch ----------------------------------------------------
extern "C" void kernel_launch(void* const* d_in, const int* in_sizes, int n_in,
                              void* d_out, int out_size) {
    const float* x      = (const float*)d_in[0];
    const float* W1     = (const float*)d_in[1];
    const float* a_src1 = (const float*)d_in[2];
    const float* a_dst1 = (const float*)d_in[3];
    const float* b1     = (const float*)d_in[4];
    const float* W2     = (const float*)d_in[5];
    const float* a_src2 = (const float*)d_in[6];
    const float* a_dst2 = (const float*)d_in[7];
    const float* b2     = (const float*)d_in[8];
    const int*   el     = (const int*)d_in[9];
    const int* srcA = el;
    const int* dstA = el + N_EDGES;
    float* out = (float*)d_out;

    float *p_h2, *p_as1, *p_ad1, *p_aE1, *p_as2, *p_ad2, *p_aE2;
    __half *p_h1f, *p_xf, *p_w1h, *p_w1l, *p_w2h, *p_w2l, *p_o1f;
    cudaGetSymbolAddress((void**)&p_h1f, g_h1f);
    cudaGetSymbolAddress((void**)&p_h2,  g_h2);
    cudaGetSymbolAddress((void**)&p_xf,  g_xf);
    cudaGetSymbolAddress((void**)&p_w1h, g_w1h);
    cudaGetSymbolAddress((void**)&p_w1l, g_w1l);
    cudaGetSymbolAddress((void**)&p_w2h, g_w2h);
    cudaGetSymbolAddress((void**)&p_w2l, g_w2l);
    cudaGetSymbolAddress((void**)&p_o1f, g_o1f);
    cudaGetSymbolAddress((void**)&p_as1, g_as1);
    cudaGetSymbolAddress((void**)&p_ad1, g_ad1);
    cudaGetSymbolAddress((void**)&p_aE1, g_aE1);
    cudaGetSymbolAddress((void**)&p_as2, g_as2);
    cudaGetSymbolAddress((void**)&p_ad2, g_ad2);
    cudaGetSymbolAddress((void**)&p_aE2, g_aE2);

    static bool s_attr_done = false;
    if (!s_attr_done) {
        cudaFuncSetAttribute(k_gemm1, cudaFuncAttributeMaxDynamicSharedMemorySize,
                             SMEM_BYTES);
        cudaFuncSetAttribute(k_gemm2, cudaFuncAttributeMaxDynamicSharedMemorySize,
                             SMEM_BYTES);
        s_attr_done = true;
    }

    // 1: zero all accumulators (h2 float4 grid covers 6144*1024 exactly)
    k_zero_all<<<N_NODES * D_HID / 4 / 256, 256>>>(p_as1, p_ad1, p_as2, p_ad2,
                                                   (float4*)p_h2);
    // 2-3: operands for GEMM1
    k_round4<<<(N_NODES * D_IN / 4 + 255) / 256, 256>>>(
        (const float4*)x, (uint2*)p_xf, N_NODES * D_IN / 4);
    k_split4<<<(D_IN * D1 / 4 + 255) / 256, 256>>>(
        (const float4*)W1, (uint2*)p_w1h, (uint2*)p_w1l, D_IN * D1 / 4);

    // 4: GEMM1 (profiled slot): h1f = fp16(x @ W1) + fused attention dots
    dim3 g1(D1 / 128, N_NODES / 128);
    k_gemm1<<<g1, 256, SMEM_BYTES>>>(p_xf, p_w1h, p_w1l, p_h1f,
                                     p_as1, p_ad1, a_src1, a_dst1, D1, D_IN);

    // 5: W2 split (needed only by GEMM2)
    k_split4<<<(D1 * D_HID / 4 + 255) / 256, 256>>>(
        (const float4*)W2, (uint2*)p_w2h, (uint2*)p_w2l, D1 * D_HID / 4);

    // 6-9: CSR build (needed from softmax onward)
    k_zero_cnt<<<N_NODES / 256, 256>>>();
    k_count<<<N_EDGES / 256, 256>>>(dstA);
    k_scan<<<1, 1024>>>();
    k_scatter<<<N_EDGES / 256, 256>>>(dstA);

    // Layer 1 edge ops
    k_softmax<<<N_NODES, 32 * H1>>>(srcA, p_as1, p_ad1, p_aE1, H1);
    dim3 ga1(N_NODES, H1);
    k_aggregate_l1<<<ga1, 192>>>(srcA, p_h1f, p_aE1, b1, p_o1f);

    // Layer 2: h2 = out1 @ W2 (split-K=2, atomic accumulate), attn fused
    dim3 g2(D_HID / 128, N_NODES / 128, 2);
    k_gemm2<<<g2, 256, SMEM_BYTES>>>(p_o1f, p_w2h, p_w2l, p_h2,
                                     p_as2, p_ad2, a_src2, a_dst2, D_HID, D1, 2);
    k_softmax<<<N_NODES, 32>>>(srcA, p_as2, p_ad2, p_aE2, 1);
    k_aggregate_l2<<<N_NODES, 192>>>(srcA, p_h2, p_aE2, b2, out);
}

// round 9
// speedup vs baseline: 1.4080x; 1.2369x over previous
#include <cuda_runtime.h>
#include <cuda_fp16.h>
#include <cstdint>

#define N_NODES 8192
#define N_EDGES 65536
#define D_IN    768
#define D_HID   768
#define H1      8
#define D1      (H1 * D_HID)   // 6144

// ---------------- scratch (static device globals) ---------------------------
__device__ __half g_h1f[(size_t)N_NODES * D1];    // fp16 x@W1
__device__ float  g_h2[(size_t)N_NODES * D_HID];  // fp32 out1@W2 (atomic accum)
__device__ __half g_xf[(size_t)N_NODES * D_IN];   // fp16(x)
__device__ __half g_w1h[(size_t)D_IN * D1];
__device__ __half g_w1l[(size_t)D_IN * D1];
__device__ __half g_w2f[(size_t)D1 * D_HID];      // fp16(W2) single
__device__ __half g_o1f[(size_t)N_NODES * D1];    // fp16(out1)
__device__ float  g_as1[N_NODES * H1];
__device__ float  g_ad1[N_NODES * H1];
__device__ float  g_aE1[(size_t)N_EDGES * H1];
__device__ float  g_as2[N_NODES];
__device__ float  g_ad2[N_NODES];
__device__ float  g_aE2[N_EDGES];
__device__ int    g_cnt[N_NODES];
__device__ int    g_indptr[N_NODES + 1];
__device__ int    g_cur[N_NODES];
__device__ int    g_eord[N_EDGES];

// ---------------- one-shot zeroing (as1, ad1, as2, ad2, h2) ------------------
__global__ void k_zero_all(float* __restrict__ as1, float* __restrict__ ad1,
                           float* __restrict__ as2, float* __restrict__ ad2,
                           float4* __restrict__ h2v) {
    int i = blockIdx.x * blockDim.x + threadIdx.x;   // 0 .. 1572863
    h2v[i] = make_float4(0.f, 0.f, 0.f, 0.f);
    if (i < N_NODES * H1) { as1[i] = 0.f; ad1[i] = 0.f; }
    if (i < N_NODES) { as2[i] = 0.f; ad2[i] = 0.f; }
}

// ---------------- CSR build ------------------------------------------------
__global__ void k_zero_cnt() {
    int i = blockIdx.x * blockDim.x + threadIdx.x;
    if (i < N_NODES) g_cnt[i] = 0;
}
__global__ void k_count(const int* __restrict__ dst) {
    int e = blockIdx.x * blockDim.x + threadIdx.x;
    if (e < N_EDGES) atomicAdd(&g_cnt[dst[e]], 1);
}
__global__ void k_scan() {
    __shared__ int sh[1024];
    int t = threadIdx.x;
    int base = t * 8;
    int local[8];
    int s = 0;
#pragma unroll
    for (int i = 0; i < 8; i++) { local[i] = s; s += g_cnt[base + i]; }
    sh[t] = s;
    __syncthreads();
    for (int off = 1; off < 1024; off <<= 1) {
        int v = (t >= off) ? sh[t - off] : 0;
        __syncthreads();
        sh[t] += v;
        __syncthreads();
    }
    int prefix = (t == 0) ? 0 : sh[t - 1];
#pragma unroll
    for (int i = 0; i < 8; i++) {
        int v = prefix + local[i];
        g_indptr[base + i] = v;
        g_cur[base + i] = v;
    }
    if (t == 1023) g_indptr[N_NODES] = sh[1023];
}
__global__ void k_scatter(const int* __restrict__ dst) {
    int e = blockIdx.x * blockDim.x + threadIdx.x;
    if (e < N_EDGES) {
        int d = dst[e];
        int p = atomicAdd(&g_cur[d], 1);
        g_eord[p] = e;
    }
}

// ---------------- fp32 -> fp16 round / split ---------------------------------
__global__ void k_round4(const float4* __restrict__ in, uint2* __restrict__ o, int n4) {
    int i = blockIdx.x * blockDim.x + threadIdx.x;
    if (i >= n4) return;
    float4 v = in[i];
    __half2 lo = __floats2half2_rn(v.x, v.y);
    __half2 hi = __floats2half2_rn(v.z, v.w);
    uint2 r;
    r.x = *(uint32_t*)&lo;
    r.y = *(uint32_t*)&hi;
    o[i] = r;
}
__global__ void k_split4(const float4* __restrict__ in,
                         uint2* __restrict__ hi, uint2* __restrict__ lo, int n4) {
    int i = blockIdx.x * blockDim.x + threadIdx.x;
    if (i >= n4) return;
    float4 v = in[i];
    __half hx = __float2half_rn(v.x), hy = __float2half_rn(v.y);
    __half hz = __float2half_rn(v.z), hw = __float2half_rn(v.w);
    __half lx = __float2half_rn(v.x - __half2float(hx));
    __half ly = __float2half_rn(v.y - __half2float(hy));
    __half lz = __float2half_rn(v.z - __half2float(hz));
    __half lw = __float2half_rn(v.w - __half2float(hw));
    uint2 hv, lv;
    hv.x = ((uint32_t)__half_as_ushort(hy) << 16) | __half_as_ushort(hx);
    hv.y = ((uint32_t)__half_as_ushort(hw) << 16) | __half_as_ushort(hz);
    lv.x = ((uint32_t)__half_as_ushort(ly) << 16) | __half_as_ushort(lx);
    lv.y = ((uint32_t)__half_as_ushort(lw) << 16) | __half_as_ushort(lz);
    hi[i] = hv;
    lo[i] = lv;
}

// ---------------- tensor-core GEMM cores --------------------------------------
// BK=64, 2-stage cp.async pipeline, BM=BN=128, 8 warps (4x2), 2 CTAs/SM.
#define BKC 64
#define A_PAD 72                   // 64 data + 8 pad (halfs)
#define B_PAD 136                  // 128 data + 8 pad
#define A_HALFS (128 * A_PAD)      // 9216
#define B_HALFS (BKC * B_PAD)      // 8704
// 2-product (gemm1): A + B hi + B lo
#define STG2_HALFS (A_HALFS + 2 * B_HALFS)   // 26624
#define SMEM2_BYTES (2 * STG2_HALFS * 2)     // 106496
// 1-product (gemm2): A + B hi
#define STG1_HALFS (A_HALFS + B_HALFS)       // 17920
#define SMEM1_BYTES (2 * STG1_HALFS * 2)     // 71680

#define LDSM4(R, addr) \
    asm volatile("ldmatrix.sync.aligned.m8n8.x4.shared.b16 {%0,%1,%2,%3}, [%4];" \
        : "=r"(R[0]), "=r"(R[1]), "=r"(R[2]), "=r"(R[3]) : "r"(addr))

#define LDSM4T(R0, R1, R2, R3, addr) \
    asm volatile("ldmatrix.sync.aligned.m8n8.x4.trans.shared.b16 {%0,%1,%2,%3}, [%4];" \
        : "=r"(R0), "=r"(R1), "=r"(R2), "=r"(R3) : "r"(addr))

#define MMA16816(D, A, B) \
    asm volatile("mma.sync.aligned.m16n8k16.row.col.f32.f16.f16.f32 " \
        "{%0,%1,%2,%3}, {%4,%5,%6,%7}, {%8,%9}, {%0,%1,%2,%3};" \
        : "+f"(D[0]), "+f"(D[1]), "+f"(D[2]), "+f"(D[3]) \
        : "r"(A[0]), "r"(A[1]), "r"(A[2]), "r"(A[3]), "r"(B[0]), "r"(B[1]))

__device__ __forceinline__ void cp16(uint32_t saddr, const void* g) {
    asm volatile("cp.async.cg.shared.global [%0], [%1], 16;" :: "r"(saddr), "l"(g));
}

// Shared prologue: thread/warp coords + accumulator init.
#define GEMM_PROLOGUE()                                                             \
    extern __shared__ __half smem[];                                               \
    const uint32_t sbase = (uint32_t)__cvta_generic_to_shared(smem);                \
    const int tid = threadIdx.x;                                                    \
    const int lane = tid & 31;                                                      \
    const int wid = tid >> 5;                                                       \
    const int wm = (wid & 3) * 32;                                                  \
    const int wn = (wid >> 2) * 64;                                                 \
    const int bm = blockIdx.y * 128;                                                \
    const int bn = blockIdx.x * 128;                                                \
    float c[2][8][4];                                                               \
    _Pragma("unroll") for (int mi = 0; mi < 2; mi++)                                \
        _Pragma("unroll") for (int nj = 0; nj < 8; nj++)                            \
            _Pragma("unroll") for (int q = 0; q < 4; q++) c[mi][nj][q] = 0.f;

// 2-product mainloop (gemm1). Exact copy plan: A 4 chunks/t, B hi+lo 4 each.
#define GEMM_MAINLOOP_2P(Af, Bh, Bl, Kdim, NKT)                                     \
    GEMM_PROLOGUE()                                                                 \
    auto load_stage = [&](int stage, int kt) {                                      \
        uint32_t aF = sbase + stage * STG2_HALFS * 2;                               \
        uint32_t bHs = aF + A_HALFS * 2;                                            \
        uint32_t bLs = bHs + B_HALFS * 2;                                           \
        _Pragma("unroll") for (int i = 0; i < 4; i++) {                             \
            int idx = tid + i * 256;                                                \
            int ar = idx >> 3, ac = (idx & 7) * 8;                                  \
            cp16(aF + (ar * A_PAD + ac) * 2,                                        \
                 (Af) + (size_t)(bm + ar) * (Kdim) + kt + ac);                      \
        }                                                                           \
        _Pragma("unroll") for (int i = 0; i < 4; i++) {                             \
            int idx = tid + i * 256;                                                \
            int br = idx >> 4, bc = (idx & 15) * 8;                                 \
            size_t gb = (size_t)(kt + br) * N + bn + bc;                            \
            uint32_t sb = (br * B_PAD + bc) * 2;                                    \
            cp16(bHs + sb, (Bh) + gb);                                              \
            cp16(bLs + sb, (Bl) + gb);                                              \
        }                                                                           \
        asm volatile("cp.async.commit_group;");                                     \
    };                                                                              \
    load_stage(0, 0);                                                               \
    for (int it = 0; it < (NKT); it++) {                                            \
        int stage = it & 1;                                                         \
        if (it + 1 < (NKT)) {                                                       \
            load_stage(stage ^ 1, (it + 1) * BKC);                                  \
            asm volatile("cp.async.wait_group 1;");                                 \
        } else {                                                                    \
            asm volatile("cp.async.wait_group 0;");                                 \
        }                                                                           \
        __syncthreads();                                                            \
        uint32_t aF = sbase + stage * STG2_HALFS * 2;                               \
        uint32_t bHs = aF + A_HALFS * 2;                                            \
        uint32_t bLs = bHs + B_HALFS * 2;                                           \
        _Pragma("unroll")                                                           \
        for (int ks = 0; ks < BKC; ks += 16) {                                      \
            uint32_t af[2][4];                                                      \
            _Pragma("unroll") for (int mi = 0; mi < 2; mi++) {                      \
                uint32_t off = ((wm + mi * 16 + (lane & 15)) * A_PAD + ks +         \
                                (lane >> 4) * 8) * 2;                               \
                LDSM4(af[mi], aF + off);                                            \
            }                                                                       \
            uint32_t bfh[8][2], bfl[8][2];                                          \
            int gq = lane >> 3;                                                     \
            int brow = ks + (lane & 7) + (gq & 1) * 8;                              \
            int bcol_base = wn + (gq >> 1) * 8;                                     \
            _Pragma("unroll") for (int nj2 = 0; nj2 < 4; nj2++) {                   \
                uint32_t off = (brow * B_PAD + bcol_base + nj2 * 16) * 2;           \
                LDSM4T(bfh[nj2 * 2][0], bfh[nj2 * 2][1],                            \
                       bfh[nj2 * 2 + 1][0], bfh[nj2 * 2 + 1][1], bHs + off);        \
                LDSM4T(bfl[nj2 * 2][0], bfl[nj2 * 2][1],                            \
                       bfl[nj2 * 2 + 1][0], bfl[nj2 * 2 + 1][1], bLs + off);        \
            }                                                                       \
            _Pragma("unroll") for (int mi = 0; mi < 2; mi++)                        \
                _Pragma("unroll") for (int nj = 0; nj < 8; nj++) {                  \
                    MMA16816(c[mi][nj], af[mi], bfh[nj]);                           \
                    MMA16816(c[mi][nj], af[mi], bfl[nj]);                           \
                }                                                                   \
        }                                                                           \
        __syncthreads();                                                            \
    }

// 1-product mainloop (gemm2): single fp16 B, half the MMAs and B traffic.
#define GEMM_MAINLOOP_1P(Af, Bh, Kdim, NKT)                                         \
    GEMM_PROLOGUE()                                                                 \
    auto load_stage = [&](int stage, int kt) {                                      \
        uint32_t aF = sbase + stage * STG1_HALFS * 2;                               \
        uint32_t bHs = aF + A_HALFS * 2;                                            \
        _Pragma("unroll") for (int i = 0; i < 4; i++) {                             \
            int idx = tid + i * 256;                                                \
            int ar = idx >> 3, ac = (idx & 7) * 8;                                  \
            cp16(aF + (ar * A_PAD + ac) * 2,                                        \
                 (Af) + (size_t)(bm + ar) * (Kdim) + kt + ac);                      \
        }                                                                           \
        _Pragma("unroll") for (int i = 0; i < 4; i++) {                             \
            int idx = tid + i * 256;                                                \
            int br = idx >> 4, bc = (idx & 15) * 8;                                 \
            cp16(bHs + (br * B_PAD + bc) * 2,                                       \
                 (Bh) + (size_t)(kt + br) * N + bn + bc);                           \
        }                                                                           \
        asm volatile("cp.async.commit_group;");                                     \
    };                                                                              \
    load_stage(0, 0);                                                               \
    for (int it = 0; it < (NKT); it++) {                                            \
        int stage = it & 1;                                                         \
        if (it + 1 < (NKT)) {                                                       \
            load_stage(stage ^ 1, (it + 1) * BKC);                                  \
            asm volatile("cp.async.wait_group 1;");                                 \
        } else {                                                                    \
            asm volatile("cp.async.wait_group 0;");                                 \
        }                                                                           \
        __syncthreads();                                                            \
        uint32_t aF = sbase + stage * STG1_HALFS * 2;                               \
        uint32_t bHs = aF + A_HALFS * 2;                                            \
        _Pragma("unroll")                                                           \
        for (int ks = 0; ks < BKC; ks += 16) {                                      \
            uint32_t af[2][4];                                                      \
            _Pragma("unroll") for (int mi = 0; mi < 2; mi++) {                      \
                uint32_t off = ((wm + mi * 16 + (lane & 15)) * A_PAD + ks +         \
                                (lane >> 4) * 8) * 2;                               \
                LDSM4(af[mi], aF + off);                                            \
            }                                                                       \
            uint32_t bfh[8][2];                                                     \
            int gq = lane >> 3;                                                     \
            int brow = ks + (lane & 7) + (gq & 1) * 8;                              \
            int bcol_base = wn + (gq >> 1) * 8;                                     \
            _Pragma("unroll") for (int nj2 = 0; nj2 < 4; nj2++) {                   \
                uint32_t off = (brow * B_PAD + bcol_base + nj2 * 16) * 2;           \
                LDSM4T(bfh[nj2 * 2][0], bfh[nj2 * 2][1],                            \
                       bfh[nj2 * 2 + 1][0], bfh[nj2 * 2 + 1][1], bHs + off);        \
            }                                                                       \
            _Pragma("unroll") for (int mi = 0; mi < 2; mi++)                        \
                _Pragma("unroll") for (int nj = 0; nj < 8; nj++)                    \
                    MMA16816(c[mi][nj], af[mi], bfh[nj]);                           \
        }                                                                           \
        __syncthreads();                                                            \
    }

// Epilogue attention partial dots (exact fp32) + atomicAdd into as/ad.
#define GEMM_ATTN_EPILOGUE(asArr, adArr, aSvec, aDvec, Hn, headIdx)                 \
    {                                                                               \
        float ds[4] = {0.f, 0.f, 0.f, 0.f}, dd[4] = {0.f, 0.f, 0.f, 0.f};           \
        _Pragma("unroll") for (int mi = 0; mi < 2; mi++)                            \
            _Pragma("unroll") for (int nj = 0; nj < 8; nj++) {                      \
                int col = bn + wn + nj * 8 + (lane & 3) * 2;                        \
                float s0 = (aSvec)[col], s1 = (aSvec)[col + 1];                     \
                float d0 = (aDvec)[col], d1 = (aDvec)[col + 1];                     \
                ds[mi * 2 + 0] += c[mi][nj][0] * s0 + c[mi][nj][1] * s1;            \
                ds[mi * 2 + 1] += c[mi][nj][2] * s0 + c[mi][nj][3] * s1;            \
                dd[mi * 2 + 0] += c[mi][nj][0] * d0 + c[mi][nj][1] * d1;            \
                dd[mi * 2 + 1] += c[mi][nj][2] * d0 + c[mi][nj][3] * d1;            \
            }                                                                       \
        _Pragma("unroll") for (int r = 0; r < 4; r++) {                             \
            ds[r] += __shfl_xor_sync(0xffffffffu, ds[r], 1);                        \
            ds[r] += __shfl_xor_sync(0xffffffffu, ds[r], 2);                        \
            dd[r] += __shfl_xor_sync(0xffffffffu, dd[r], 1);                        \
            dd[r] += __shfl_xor_sync(0xffffffffu, dd[r], 2);                        \
        }                                                                           \
        if ((lane & 3) == 0) {                                                      \
            _Pragma("unroll") for (int mi = 0; mi < 2; mi++) {                      \
                int ra = bm + wm + mi * 16 + (lane >> 2);                           \
                atomicAdd(&(asArr)[(size_t)ra * (Hn) + (headIdx)], ds[mi * 2 + 0]); \
                atomicAdd(&(asArr)[(size_t)(ra + 8) * (Hn) + (headIdx)], ds[mi * 2 + 1]); \
                atomicAdd(&(adArr)[(size_t)ra * (Hn) + (headIdx)], dd[mi * 2 + 0]); \
                atomicAdd(&(adArr)[(size_t)(ra + 8) * (Hn) + (headIdx)], dd[mi * 2 + 1]); \
            }                                                                       \
        }                                                                           \
    }

// GEMM1: 2-product, C fp16 direct store + attention dots for H1 heads.
__global__ __launch_bounds__(256, 2) void k_gemm1(
    const __half* __restrict__ Af,
    const __half* __restrict__ Bh, const __half* __restrict__ Bl,
    __half* __restrict__ Cf, float* __restrict__ asArr, float* __restrict__ adArr,
    const float* __restrict__ aSvec, const float* __restrict__ aDvec,
    int N, int K) {
    GEMM_MAINLOOP_2P(Af, Bh, Bl, K, K / BKC)

    const int head = bn / D_HID;
    GEMM_ATTN_EPILOGUE(asArr, adArr, aSvec, aDvec, H1, head)

#pragma unroll
    for (int mi = 0; mi < 2; mi++) {
        int row0 = bm + wm + mi * 16 + (lane >> 2);
#pragma unroll
        for (int nj = 0; nj < 8; nj++) {
            int col = bn + wn + nj * 8 + (lane & 3) * 2;
            __half2 p0 = __floats2half2_rn(c[mi][nj][0], c[mi][nj][1]);
            __half2 p1 = __floats2half2_rn(c[mi][nj][2], c[mi][nj][3]);
            *(__half2*)(Cf + (size_t)row0 * N + col) = p0;
            *(__half2*)(Cf + (size_t)(row0 + 8) * N + col) = p1;
        }
    }
}

// GEMM2: 1-product, split-K over blockIdx.z, fp32 atomicAdd + attn dots (H=1).
__global__ __launch_bounds__(256, 2) void k_gemm2(
    const __half* __restrict__ Afull,
    const __half* __restrict__ Bfull,
    float* __restrict__ C, float* __restrict__ asArr, float* __restrict__ adArr,
    const float* __restrict__ aSvec, const float* __restrict__ aDvec,
    int N, int Kfull, int ksplit) {
    const int kpart = Kfull / ksplit;
    const int kbase = blockIdx.z * kpart;
    const __half* Af = Afull + kbase;            // row stride remains Kfull
    const __half* Bh = Bfull + (size_t)kbase * N;

    GEMM_MAINLOOP_1P(Af, Bh, Kfull, kpart / BKC)

    GEMM_ATTN_EPILOGUE(asArr, adArr, aSvec, aDvec, 1, 0)

#pragma unroll
    for (int mi = 0; mi < 2; mi++) {
        int row0 = bm + wm + mi * 16 + (lane >> 2);
#pragma unroll
        for (int nj = 0; nj < 8; nj++) {
            int col = bn + wn + nj * 8 + (lane & 3) * 2;
            float* p0 = C + (size_t)row0 * N + col;
            float* p1 = C + (size_t)(row0 + 8) * N + col;
            atomicAdd(p0, c[mi][nj][0]);
            atomicAdd(p0 + 1, c[mi][nj][1]);
            atomicAdd(p1, c[mi][nj][2]);
            atomicAdd(p1 + 1, c[mi][nj][3]);
        }
    }
}

// ---------------- segment softmax over CSR -----------------------------------
__global__ void k_softmax(const int* __restrict__ src,
                          const float* __restrict__ as,
                          const float* __restrict__ ad,
                          float* __restrict__ aE, int H) {
    int n = blockIdx.x;
    int hh = threadIdx.x >> 5;
    int lane = threadIdx.x & 31;
    int beg = g_indptr[n], end = g_indptr[n + 1];
    if (beg == end) return;
    float adn = ad[(size_t)n * H + hh];

    float m = -3.4e38f;
    for (int j = beg + lane; j < end; j += 32) {
        int s = src[g_eord[j]];
        float v = as[(size_t)s * H + hh] + adn;
        v = v > 0.f ? v : 0.2f * v;
        m = fmaxf(m, v);
    }
#pragma unroll
    for (int o = 16; o; o >>= 1) m = fmaxf(m, __shfl_xor_sync(0xffffffffu, m, o));

    float sum = 0.f;
    for (int j = beg + lane; j < end; j += 32) {
        int s = src[g_eord[j]];
        float v = as[(size_t)s * H + hh] + adn;
        v = v > 0.f ? v : 0.2f * v;
        float ex = __expf(v - m);
        aE[(size_t)j * H + hh] = ex;
        sum += ex;
    }
#pragma unroll
    for (int o = 16; o; o >>= 1) sum += __shfl_xor_sync(0xffffffffu, sum, o);

    float inv = 1.f / (sum + 1e-16f);
    for (int j = beg + lane; j < end; j += 32)
        aE[(size_t)j * H + hh] *= inv;
}

// ---------------- aggregation layer 1: fp16 gather -> fp16 out ---------------
__global__ __launch_bounds__(192) void k_aggregate_l1(const int* __restrict__ src,
                                                      const __half* __restrict__ hf,
                                                      const float* __restrict__ aE,
                                                      const float* __restrict__ bias,
                                                      __half* __restrict__ of) {
    int n = blockIdx.x;
    int hh = blockIdx.y;
    int t = threadIdx.x;
    int beg = g_indptr[n], end = g_indptr[n + 1];

    float a0 = 0.f, a1 = 0.f, a2 = 0.f, a3 = 0.f;
    for (int j = beg; j < end; j++) {
        int s = src[g_eord[j]];
        float w = aE[(size_t)j * H1 + hh];
        uint2 rv = *(const uint2*)(hf + ((size_t)s * H1 + hh) * D_HID + t * 4);
        __half2 h01 = *(__half2*)&rv.x;
        __half2 h23 = *(__half2*)&rv.y;
        float2 f01 = __half22float2(h01);
        float2 f23 = __half22float2(h23);
        a0 += f01.x * w;
        a1 += f01.y * w;
        a2 += f23.x * w;
        a3 += f23.y * w;
    }
    const float4 bb = *(const float4*)(bias + (size_t)hh * D_HID + t * 4);
    float v0 = a0 + bb.x;
    float v1 = a1 + bb.y;
    float v2 = a2 + bb.z;
    float v3 = a3 + bb.w;
    v0 = v0 > 0.f ? v0 : (__expf(v0) - 1.f);
    v1 = v1 > 0.f ? v1 : (__expf(v1) - 1.f);
    v2 = v2 > 0.f ? v2 : (__expf(v2) - 1.f);
    v3 = v3 > 0.f ? v3 : (__expf(v3) - 1.f);
    __half2 lo = __floats2half2_rn(v0, v1);
    __half2 hi = __floats2half2_rn(v2, v3);
    uint2 r;
    r.x = *(uint32_t*)&lo;
    r.y = *(uint32_t*)&hi;
    *(uint2*)(of + ((size_t)n * H1 + hh) * D_HID + t * 4) = r;
}

// ---------------- aggregation layer 2: fp32, no ELU ---------------------------
__global__ __launch_bounds__(192) void k_aggregate_l2(const int* __restrict__ src,
                                                      const float* __restrict__ h,
                                                      const float* __restrict__ aE,
                                                      const float* __restrict__ bias,
                                                      float* __restrict__ out) {
    int n = blockIdx.x;
    int t = threadIdx.x;
    int beg = g_indptr[n], end = g_indptr[n + 1];

    float a0 = 0.f, a1 = 0.f, a2 = 0.f, a3 = 0.f;
    for (int j = beg; j < end; j++) {
        int s = src[g_eord[j]];
        float w = aE[j];
        float4 v = *(const float4*)(h + (size_t)s * D_HID + t * 4);
        a0 += v.x * w;
        a1 += v.y * w;
        a2 += v.z * w;
        a3 += v.w * w;
    }
    const float4 bb = *(const float4*)(bias + t * 4);
    float4 o = {a0 + bb.x, a1 + bb.y, a2 + bb.z, a3 + bb.w};
    *(float4*)(out + (size_t)n * D_HID + t * 4) = o;
}

// ---------------- launch ----------------------------------------------------
extern "C" void kernel_launch(void* const* d_in, const int* in_sizes, int n_in,
                              void* d_out, int out_size) {
    const float* x      = (const float*)d_in[0];
    const float* W1     = (const float*)d_in[1];
    const float* a_src1 = (const float*)d_in[2];
    const float* a_dst1 = (const float*)d_in[3];
    const float* b1     = (const float*)d_in[4];
    const float* W2     = (const float*)d_in[5];
    const float* a_src2 = (const float*)d_in[6];
    const float* a_dst2 = (const float*)d_in[7];
    const float* b2     = (const float*)d_in[8];
    const int*   el     = (const int*)d_in[9];
    const int* srcA = el;
    const int* dstA = el + N_EDGES;
    float* out = (float*)d_out;

    float *p_h2, *p_as1, *p_ad1, *p_aE1, *p_as2, *p_ad2, *p_aE2;
    __half *p_h1f, *p_xf, *p_w1h, *p_w1l, *p_w2f, *p_o1f;
    cudaGetSymbolAddress((void**)&p_h1f, g_h1f);
    cudaGetSymbolAddress((void**)&p_h2,  g_h2);
    cudaGetSymbolAddress((void**)&p_xf,  g_xf);
    cudaGetSymbolAddress((void**)&p_w1h, g_w1h);
    cudaGetSymbolAddress((void**)&p_w1l, g_w1l);
    cudaGetSymbolAddress((void**)&p_w2f, g_w2f);
    cudaGetSymbolAddress((void**)&p_o1f, g_o1f);
    cudaGetSymbolAddress((void**)&p_as1, g_as1);
    cudaGetSymbolAddress((void**)&p_ad1, g_ad1);
    cudaGetSymbolAddress((void**)&p_aE1, g_aE1);
    cudaGetSymbolAddress((void**)&p_as2, g_as2);
    cudaGetSymbolAddress((void**)&p_ad2, g_ad2);
    cudaGetSymbolAddress((void**)&p_aE2, g_aE2);

    static bool s_attr_done = false;
    if (!s_attr_done) {
        cudaFuncSetAttribute(k_gemm1, cudaFuncAttributeMaxDynamicSharedMemorySize,
                             SMEM2_BYTES);
        cudaFuncSetAttribute(k_gemm2, cudaFuncAttributeMaxDynamicSharedMemorySize,
                             SMEM1_BYTES);
        s_attr_done = true;
    }

    // 1: zero all accumulators (h2 float4 grid covers 6144*1024 exactly)
    k_zero_all<<<N_NODES * D_HID / 4 / 256, 256>>>(p_as1, p_ad1, p_as2, p_ad2,
                                                   (float4*)p_h2);
    // 2-3: operands for GEMM1
    k_round4<<<(N_NODES * D_IN / 4 + 255) / 256, 256>>>(
        (const float4*)x, (uint2*)p_xf, N_NODES * D_IN / 4);
    k_split4<<<(D_IN * D1 / 4 + 255) / 256, 256>>>(
        (const float4*)W1, (uint2*)p_w1h, (uint2*)p_w1l, D_IN * D1 / 4);

    // 4: GEMM1 (profiled slot): h1f = fp16(x @ W1) + fused attention dots
    dim3 g1(D1 / 128, N_NODES / 128);
    k_gemm1<<<g1, 256, SMEM2_BYTES>>>(p_xf, p_w1h, p_w1l, p_h1f,
                                      p_as1, p_ad1, a_src1, a_dst1, D1, D_IN);

    // 5: W2 round (single fp16, no split)
    k_round4<<<(D1 * D_HID / 4 + 255) / 256, 256>>>(
        (const float4*)W2, (uint2*)p_w2f, D1 * D_HID / 4);

    // 6-9: CSR build (needed from softmax onward)
    k_zero_cnt<<<N_NODES / 256, 256>>>();
    k_count<<<N_EDGES / 256, 256>>>(dstA);
    k_scan<<<1, 1024>>>();
    k_scatter<<<N_EDGES / 256, 256>>>(dstA);

    // Layer 1 edge ops
    k_softmax<<<N_NODES, 32 * H1>>>(srcA, p_as1, p_ad1, p_aE1, H1);
    dim3 ga1(N_NODES, H1);
    k_aggregate_l1<<<ga1, 192>>>(srcA, p_h1f, p_aE1, b1, p_o1f);

    // Layer 2: h2 = out1 @ W2 (1-product, split-K=3, atomic accumulate)
    dim3 g2(D_HID / 128, N_NODES / 128, 3);
    k_gemm2<<<g2, 256, SMEM1_BYTES>>>(p_o1f, p_w2f, p_h2,
                                      p_as2, p_ad2, a_src2, a_dst2, D_HID, D1, 3);
    k_softmax<<<N_NODES, 32>>>(srcA, p_as2, p_ad2, p_aE2, 1);
    k_aggregate_l2<<<N_NODES, 192>>>(srcA, p_h2, p_aE2, b2, out);
}